// round 1
// baseline (speedup 1.0000x reference)
#include <cuda_runtime.h>

// Problem constants
#define R_   64
#define C_   512
#define E_   768
#define H_   12
#define D_   64
#define NTOK (R_ * C_)          // 32768 tokens (B=1)

// Output layout inside d_out (flattened tuple: output, attn_probs, l)
#define OFF_OUT   0
#define OFF_PROBS ((size_t)NTOK * E_)                       // 25165824
#define OFF_L     (OFF_PROBS + (size_t)H_ * C_ * C_)        // 28311552

// Scratch (device globals -- no allocation allowed)
__device__ float g_q[(size_t)NTOK * E_];
__device__ float g_k[(size_t)NTOK * E_];
__device__ float g_v[(size_t)NTOK * E_];
__device__ float g_ctx[(size_t)NTOK * E_];
__device__ float g_logits[(size_t)H_ * C_ * C_];

// ---------------------------------------------------------------------------
// GEMM NT: C[m][n] = alpha * ( sum_k A[m][k] * B[n][k] + bias[n] )
// A: [M,K] row-major, B: [N,K] row-major. M%128==0, N%128==0, K%16==0.
// 128x128 block tile, BK=16, 256 threads, 8x8 micro-tile.
// ---------------------------------------------------------------------------
__global__ __launch_bounds__(256) void gemm_nt_kernel(
    const float* __restrict__ A, const float* __restrict__ Bw,
    const float* __restrict__ bias, float* __restrict__ Co,
    int M, int N, int K, float alpha)
{
    const int BM = 128, BN = 128, BK = 16;
    __shared__ float As[BK][BM + 4];
    __shared__ float Bs[BK][BN + 4];

    int t  = threadIdx.x;
    int bm = blockIdx.x * BM;
    int bn = blockIdx.y * BN;
    int tx = t % 16;          // 0..15 -> 8 cols each
    int ty = t / 16;          // 0..15 -> 8 rows each

    int lr = t / 4;           // 0..63 : tile row for loads
    int lk = (t % 4) * 4;     // 0,4,8,12 : k offset for float4 load

    float acc[8][8];
    #pragma unroll
    for (int i = 0; i < 8; i++)
        #pragma unroll
        for (int j = 0; j < 8; j++) acc[i][j] = 0.f;

    for (int k0 = 0; k0 < K; k0 += BK) {
        #pragma unroll
        for (int it = 0; it < 2; it++) {
            int row = lr + it * 64;
            float4 va = *(const float4*)&A [(size_t)(bm + row) * K + k0 + lk];
            As[lk + 0][row] = va.x; As[lk + 1][row] = va.y;
            As[lk + 2][row] = va.z; As[lk + 3][row] = va.w;
            float4 vb = *(const float4*)&Bw[(size_t)(bn + row) * K + k0 + lk];
            Bs[lk + 0][row] = vb.x; Bs[lk + 1][row] = vb.y;
            Bs[lk + 2][row] = vb.z; Bs[lk + 3][row] = vb.w;
        }
        __syncthreads();

        #pragma unroll
        for (int kk = 0; kk < BK; kk++) {
            float a[8], b[8];
            #pragma unroll
            for (int i = 0; i < 8; i++) a[i] = As[kk][ty * 8 + i];
            #pragma unroll
            for (int j = 0; j < 8; j++) b[j] = Bs[kk][tx * 8 + j];
            #pragma unroll
            for (int i = 0; i < 8; i++)
                #pragma unroll
                for (int j = 0; j < 8; j++)
                    acc[i][j] = fmaf(a[i], b[j], acc[i][j]);
        }
        __syncthreads();
    }

    float bb[8];
    #pragma unroll
    for (int j = 0; j < 8; j++) bb[j] = bias[bn + tx * 8 + j];

    #pragma unroll
    for (int i = 0; i < 8; i++) {
        size_t rowoff = (size_t)(bm + ty * 8 + i) * N + bn + tx * 8;
        #pragma unroll
        for (int j = 0; j < 8; j += 4) {
            float4 o;
            o.x = alpha * (acc[i][j + 0] + bb[j + 0]);
            o.y = alpha * (acc[i][j + 1] + bb[j + 1]);
            o.z = alpha * (acc[i][j + 2] + bb[j + 2]);
            o.w = alpha * (acc[i][j + 3] + bb[j + 3]);
            *(float4*)&Co[rowoff + j] = o;
        }
    }
}

// ---------------------------------------------------------------------------
// Tied-row logits: lg[h][i][j] = sum_{r,d} q[r][i][h*64+d] * k[r][j][h*64+d]
// grid: (i_tile=8, j_tile=8, h=12). 64x64 tile, 256 threads, 4x4 micro.
// ---------------------------------------------------------------------------
__global__ __launch_bounds__(256) void logits_kernel(
    const float* __restrict__ q, const float* __restrict__ kq,
    float* __restrict__ lg)
{
    __shared__ float Qs[64][68];  // [d][i]
    __shared__ float Ks[64][68];  // [d][j]

    int i0 = blockIdx.x * 64;
    int j0 = blockIdx.y * 64;
    int h  = blockIdx.z;
    int t  = threadIdx.x;
    int tx = t % 16, ty = t / 16;
    int li = t / 16;            // 0..15
    int ld = (t % 16) * 4;      // d offset (float4)

    float acc[4][4];
    #pragma unroll
    for (int i = 0; i < 4; i++)
        #pragma unroll
        for (int j = 0; j < 4; j++) acc[i][j] = 0.f;

    for (int r = 0; r < R_; r++) {
        const float* qb = q  + ((size_t)r * C_) * E_ + h * D_;
        const float* kb = kq + ((size_t)r * C_) * E_ + h * D_;
        #pragma unroll
        for (int it = 0; it < 4; it++) {
            int row = li + it * 16;
            float4 va = *(const float4*)&qb[(size_t)(i0 + row) * E_ + ld];
            Qs[ld + 0][row] = va.x; Qs[ld + 1][row] = va.y;
            Qs[ld + 2][row] = va.z; Qs[ld + 3][row] = va.w;
            float4 vb = *(const float4*)&kb[(size_t)(j0 + row) * E_ + ld];
            Ks[ld + 0][row] = vb.x; Ks[ld + 1][row] = vb.y;
            Ks[ld + 2][row] = vb.z; Ks[ld + 3][row] = vb.w;
        }
        __syncthreads();

        #pragma unroll
        for (int d = 0; d < 64; d++) {
            float a[4], b[4];
            #pragma unroll
            for (int i = 0; i < 4; i++) a[i] = Qs[d][ty * 4 + i];
            #pragma unroll
            for (int j = 0; j < 4; j++) b[j] = Ks[d][tx * 4 + j];
            #pragma unroll
            for (int i = 0; i < 4; i++)
                #pragma unroll
                for (int j = 0; j < 4; j++)
                    acc[i][j] = fmaf(a[i], b[j], acc[i][j]);
        }
        __syncthreads();
    }

    #pragma unroll
    for (int i = 0; i < 4; i++) {
        size_t rowoff = ((size_t)h * C_ + i0 + ty * 4 + i) * C_ + j0 + tx * 4;
        float4 o = make_float4(acc[i][0], acc[i][1], acc[i][2], acc[i][3]);
        *(float4*)&lg[rowoff] = o;
    }
}

// ---------------------------------------------------------------------------
// Masked softmax over j (diag masked to -1e9). One block (256 thr) per (h,i).
// Writes probs in-place into lg AND into d_out attn_probs slot.
// ---------------------------------------------------------------------------
__global__ __launch_bounds__(256) void softmax_kernel(
    float* __restrict__ lg, float* __restrict__ probs_out)
{
    __shared__ float redmax[8];
    __shared__ float redsum[8];

    int row = blockIdx.x;             // h*C_ + i
    int i   = row % C_;
    float* base = lg + (size_t)row * C_;
    int t = threadIdx.x;

    float x0 = base[t];
    float x1 = base[t + 256];
    if (t == i)       x0 = -1e9f;
    if (t + 256 == i) x1 = -1e9f;

    float m = fmaxf(x0, x1);
    #pragma unroll
    for (int o = 16; o > 0; o >>= 1)
        m = fmaxf(m, __shfl_xor_sync(0xffffffffu, m, o));
    if ((t & 31) == 0) redmax[t >> 5] = m;
    __syncthreads();
    float M = redmax[0];
    #pragma unroll
    for (int w = 1; w < 8; w++) M = fmaxf(M, redmax[w]);

    float e0 = __expf(x0 - M);
    float e1 = __expf(x1 - M);
    float s = e0 + e1;
    #pragma unroll
    for (int o = 16; o > 0; o >>= 1)
        s += __shfl_xor_sync(0xffffffffu, s, o);
    if ((t & 31) == 0) redsum[t >> 5] = s;
    __syncthreads();
    float S = 0.f;
    #pragma unroll
    for (int w = 0; w < 8; w++) S += redsum[w];
    float inv = 1.f / S;

    float p0 = e0 * inv, p1 = e1 * inv;
    base[t]       = p0;
    base[t + 256] = p1;
    float* po = probs_out + (size_t)row * C_;
    po[t]       = p0;
    po[t + 256] = p1;
}

// ---------------------------------------------------------------------------
// Context: ctx[r][i][h*64+d] = sum_j probs[h][i][j] * v[r][j][h*64+d]
// grid: (i_tile=8, h=12, r=64). 64(i) x 64(d) tile, K=512 over j, BK=64.
// ---------------------------------------------------------------------------
__global__ __launch_bounds__(256) void context_kernel(
    const float* __restrict__ probs, const float* __restrict__ v,
    float* __restrict__ ctx)
{
    __shared__ float Ps[64][68];  // [j][i]
    __shared__ float Vs[64][64];  // [j][d]

    int i0 = blockIdx.x * 64;
    int h  = blockIdx.y;
    int r  = blockIdx.z;
    int t  = threadIdx.x;
    int tx = t % 16, ty = t / 16;
    int li  = t / 16;
    int lc4 = (t % 16) * 4;

    float acc[4][4];
    #pragma unroll
    for (int i = 0; i < 4; i++)
        #pragma unroll
        for (int j = 0; j < 4; j++) acc[i][j] = 0.f;

    for (int j0 = 0; j0 < C_; j0 += 64) {
        #pragma unroll
        for (int it = 0; it < 4; it++) {
            int row = li + it * 16;
            // P tile: probs[h][i0+row][j0 + lc4 .. +3] -> Ps[j][i] (transposed)
            float4 p = *(const float4*)&probs[((size_t)h * C_ + i0 + row) * C_ + j0 + lc4];
            Ps[lc4 + 0][row] = p.x; Ps[lc4 + 1][row] = p.y;
            Ps[lc4 + 2][row] = p.z; Ps[lc4 + 3][row] = p.w;
            // V tile: v[r][j0+row][h*64 + lc4 .. +3] -> Vs[j][d] (direct)
            float4 vv = *(const float4*)&v[((size_t)r * C_ + j0 + row) * E_ + h * D_ + lc4];
            *(float4*)&Vs[row][lc4] = vv;
        }
        __syncthreads();

        #pragma unroll
        for (int jj = 0; jj < 64; jj++) {
            float a[4], b[4];
            #pragma unroll
            for (int i = 0; i < 4; i++) a[i] = Ps[jj][ty * 4 + i];
            #pragma unroll
            for (int d = 0; d < 4; d++) b[d] = Vs[jj][tx * 4 + d];
            #pragma unroll
            for (int i = 0; i < 4; i++)
                #pragma unroll
                for (int d = 0; d < 4; d++)
                    acc[i][d] = fmaf(a[i], b[d], acc[i][d]);
        }
        __syncthreads();
    }

    #pragma unroll
    for (int i = 0; i < 4; i++) {
        size_t off = ((size_t)r * C_ + i0 + ty * 4 + i) * E_ + h * D_ + tx * 4;
        float4 o = make_float4(acc[i][0], acc[i][1], acc[i][2], acc[i][3]);
        *(float4*)&ctx[off] = o;
    }
}

// ---------------------------------------------------------------------------
// Copy l (12 floats) to tail of d_out.
// ---------------------------------------------------------------------------
__global__ void copy_l_kernel(const float* __restrict__ l, float* __restrict__ out)
{
    int t = threadIdx.x;
    if (t < H_) out[t] = l[t];
}

// ---------------------------------------------------------------------------
extern "C" void kernel_launch(void* const* d_in, const int* in_sizes, int n_in,
                              void* d_out, int out_size)
{
    const float* x  = (const float*)d_in[0];
    // d_in[1] = network (unused by reference output)
    const float* Wq = (const float*)d_in[2];
    const float* bq = (const float*)d_in[3];
    const float* Wk = (const float*)d_in[4];
    const float* bk = (const float*)d_in[5];
    const float* Wv = (const float*)d_in[6];
    const float* bv = (const float*)d_in[7];
    const float* Wo = (const float*)d_in[8];
    const float* bo = (const float*)d_in[9];
    const float* l  = (const float*)d_in[10];
    float* out = (float*)d_out;

    float* q   = nullptr; cudaGetSymbolAddress((void**)&q,   g_q);
    float* k   = nullptr; cudaGetSymbolAddress((void**)&k,   g_k);
    float* v   = nullptr; cudaGetSymbolAddress((void**)&v,   g_v);
    float* ctx = nullptr; cudaGetSymbolAddress((void**)&ctx, g_ctx);
    float* lg  = nullptr; cudaGetSymbolAddress((void**)&lg,  g_logits);

    const float scaling = (1.0f / 8.0f) / 8.0f;  // D^-0.5 / sqrt(R) = 1/64

    dim3 ggrid(NTOK / 128, E_ / 128);  // (256, 6)
    gemm_nt_kernel<<<ggrid, 256>>>(x, Wq, bq, q, NTOK, E_, E_, scaling);
    gemm_nt_kernel<<<ggrid, 256>>>(x, Wk, bk, k, NTOK, E_, E_, 1.0f);
    gemm_nt_kernel<<<ggrid, 256>>>(x, Wv, bv, v, NTOK, E_, E_, 1.0f);

    dim3 lgrid(C_ / 64, C_ / 64, H_);  // (8, 8, 12)
    logits_kernel<<<lgrid, 256>>>(q, k, lg);

    softmax_kernel<<<H_ * C_, 256>>>(lg, out + OFF_PROBS);

    dim3 cgrid(C_ / 64, H_, R_);       // (8, 12, 64)
    context_kernel<<<cgrid, 256>>>(lg, v, ctx);

    gemm_nt_kernel<<<ggrid, 256>>>(ctx, Wo, bo, out + OFF_OUT, NTOK, E_, E_, 1.0f);

    copy_l_kernel<<<1, 32>>>(l, out + OFF_L);
}

// round 5
// speedup vs baseline: 3.1695x; 3.1695x over previous
#include <cuda_runtime.h>
#include <cstdint>

// Problem constants
#define R_   64
#define C_   512
#define E_   768
#define H_   12
#define HD_  64
#define NTOK (R_ * C_)          // 32768 tokens (B=1)
#define BKC  32                 // k-chunk size

// Output layout inside d_out (flattened tuple: output, attn_probs, l)
#define OFF_PROBS ((size_t)NTOK * E_)
#define OFF_L     (OFF_PROBS + (size_t)H_ * C_ * C_)

// Scratch (device globals -- no allocation allowed)
__device__ float g_q  [(size_t)NTOK * E_];
__device__ float g_k  [(size_t)NTOK * E_];
__device__ float g_vt [(size_t)NTOK * E_];   // [r][h][d][c] transposed V
__device__ float g_ctx[(size_t)NTOK * E_];
__device__ float g_lg [(size_t)H_ * C_ * C_];

// ============================ helpers ============================
__device__ __forceinline__ uint32_t smem_u32(const void* p) {
    uint32_t a;
    asm("{ .reg .u64 t; cvta.to.shared.u64 t, %1; cvt.u32.u64 %0, t; }" : "=r"(a) : "l"(p));
    return a;
}
__device__ __forceinline__ void cp16(uint32_t saddr, const float* gptr) {
    size_t ga = __cvta_generic_to_global(gptr);
    asm volatile("cp.async.cg.shared.global [%0], [%1], 16;" :: "r"(saddr), "l"(ga) : "memory");
}
__device__ __forceinline__ uint32_t tf32_of(uint32_t raw) {
    uint32_t o;
    asm("cvt.rna.tf32.f32 %0, %1;" : "=r"(o) : "f"(__uint_as_float(raw)));
    return o;
}
// D += A(16x8,row) * B(8x8,col)  -- tf32 inputs, fp32 accum
__device__ __forceinline__ void mma8(float* c, const uint32_t* a, const uint32_t* b) {
    asm volatile(
        "mma.sync.aligned.m16n8k8.row.col.f32.tf32.tf32.f32 "
        "{%0,%1,%2,%3}, {%4,%5,%6,%7}, {%8,%9}, {%0,%1,%2,%3};"
        : "+f"(c[0]), "+f"(c[1]), "+f"(c[2]), "+f"(c[3])
        : "r"(a[0]), "r"(a[1]), "r"(a[2]), "r"(a[3]), "r"(b[0]), "r"(b[1]));
}

// ============================================================================
// tf32 mma.sync GEMM-NT: D[m][n] = alpha * (sum_k A[m][k]*B[n][k] + bias[n])
//   MODE 0 (PROJ):   A=x[M,768], B=W[768,768]. grid(M/BM, 768/BN).
//                    VT=true scatters result into v_t[r][h][d][c].
//   MODE 1 (LOGITS): per head h: D[i,j] = sum_{r,d} q[r,i,h,d]*k[r,j,h,d]
//                    grid(i/BM, j/BN, h). K=4096, chunk kc -> (r=kc>>1, dhalf=kc&1).
//   MODE 2 (CTX):    per (h,r): D[i,d] = sum_j probs[h,i,j]*v_t[r,h,d,j]
//                    grid(i/BM, h, r). K=512.
// 2-stage cp.async pipeline, BK=32, warp tile 64 x (BN/WC), m16n8k8 tf32 MMA.
// ============================================================================
template<int BM, int BN, int WC, int NCH, int MODE, bool HAS_BIAS, bool VT>
__global__ __launch_bounds__((BM / 64) * WC * 32)
void mma_gemm(const float* __restrict__ A, const float* __restrict__ B,
              const float* __restrict__ bias, float* __restrict__ D, float alpha)
{
    constexpr int WR   = BM / 64;
    constexpr int NT   = WR * WC * 32;
    constexpr int WN   = BN / WC;
    constexpr int NTL  = WN / 8;
    constexpr int LDSw = BKC + 4;               // padded row stride (words)
    constexpr int STG  = (BM + BN) * LDSw;      // words per stage
    constexpr int IA   = BM * (BKC / 4) / NT;   // A float4 loads per thread
    constexpr int IB   = BN * (BKC / 4) / NT;

    extern __shared__ __align__(16) uint32_t sm[];
    const uint32_t sbase = smem_u32(sm);
    const int tid = threadIdx.x, wid = tid >> 5, lane = tid & 31;
    const int g = lane >> 2, tq = lane & 3;
    const int wm = (wid / WC) * 64, wn = (wid % WC) * WN;

    // ---- per-CTA operand/result decode ----
    const float* A0; const float* B0; float* D0 = nullptr;
    size_t lda, ldb, ldd = 0;
    int n0 = 0, rr = 0, cc0 = 0;
    if (MODE == 0) {
        int m0 = blockIdx.x * BM; n0 = blockIdx.y * BN;
        lda = E_; ldb = E_; ldd = E_;
        A0 = A + (size_t)m0 * lda;
        B0 = B + (size_t)n0 * ldb;
        D0 = D + (size_t)m0 * ldd + n0;
        rr = m0 / C_; cc0 = m0 % C_;            // BM<=512 & aligned: one r per block
    } else if (MODE == 1) {
        int i0 = blockIdx.x * BM, j0 = blockIdx.y * BN, h = blockIdx.z;
        lda = E_; ldb = E_; ldd = C_;
        A0 = A + (size_t)i0 * E_ + h * HD_;
        B0 = B + (size_t)j0 * E_ + h * HD_;
        D0 = D + ((size_t)h * C_ + i0) * C_ + j0;
    } else {
        int i0 = blockIdx.x * BM, h = blockIdx.y, r = blockIdx.z;
        lda = C_; ldb = C_; ldd = E_;
        A0 = A + ((size_t)h * C_ + i0) * C_;
        B0 = B + ((size_t)(r * H_ + h) * HD_) * C_;
        D0 = D + ((size_t)r * C_ + i0) * E_ + h * HD_;
    }

    auto issue = [&](int kc, int s) {
        size_t koff = (MODE == 1)
            ? ((size_t)(kc >> 1) * ((size_t)C_ * E_) + (size_t)(kc & 1) * BKC)
            : (size_t)kc * BKC;
        const float* Ab = A0 + koff;
        const float* Bb = B0 + koff;
        #pragma unroll
        for (int it = 0; it < IA; it++) {
            int idx = tid + it * NT, row = idx >> 3, cw = (idx & 7) * 4;
            cp16(sbase + (uint32_t)(s * STG + row * LDSw + cw) * 4u,
                 Ab + (size_t)row * lda + cw);
        }
        #pragma unroll
        for (int it = 0; it < IB; it++) {
            int idx = tid + it * NT, row = idx >> 3, cw = (idx & 7) * 4;
            cp16(sbase + (uint32_t)(s * STG + BM * LDSw + row * LDSw + cw) * 4u,
                 Bb + (size_t)row * ldb + cw);
        }
        asm volatile("cp.async.commit_group;" ::: "memory");
    };

    float acc[4][NTL][4];
    #pragma unroll
    for (int mt = 0; mt < 4; mt++)
        #pragma unroll
        for (int nt = 0; nt < NTL; nt++)
            #pragma unroll
            for (int i = 0; i < 4; i++) acc[mt][nt][i] = 0.f;

    issue(0, 0);
    #pragma unroll 1
    for (int kc = 0; kc < NCH; kc++) {
        const int s = kc & 1;
        if (kc + 1 < NCH) {
            issue(kc + 1, s ^ 1);               // stage s^1 free (synced last iter)
            asm volatile("cp.async.wait_group 1;" ::: "memory");
        } else {
            asm volatile("cp.async.wait_group 0;" ::: "memory");
        }
        __syncthreads();                        // chunk kc visible block-wide

        const uint32_t* sA = sm + s * STG + wm * LDSw;
        const uint32_t* sB = sm + s * STG + BM * LDSw + wn * LDSw;
        #pragma unroll
        for (int ks = 0; ks < BKC / 8; ks++) {
            const int k0 = ks * 8;
            uint32_t a[4][4], b[NTL][2];
            #pragma unroll
            for (int mt = 0; mt < 4; mt++) {
                int rb = mt * 16;
                a[mt][0] = tf32_of(sA[(rb + g    ) * LDSw + k0 + tq    ]);
                a[mt][1] = tf32_of(sA[(rb + g + 8) * LDSw + k0 + tq    ]);
                a[mt][2] = tf32_of(sA[(rb + g    ) * LDSw + k0 + tq + 4]);
                a[mt][3] = tf32_of(sA[(rb + g + 8) * LDSw + k0 + tq + 4]);
            }
            #pragma unroll
            for (int nt = 0; nt < NTL; nt++) {
                int cb = nt * 8;
                b[nt][0] = tf32_of(sB[(cb + g) * LDSw + k0 + tq    ]);
                b[nt][1] = tf32_of(sB[(cb + g) * LDSw + k0 + tq + 4]);
            }
            #pragma unroll
            for (int mt = 0; mt < 4; mt++)
                #pragma unroll
                for (int nt = 0; nt < NTL; nt++)
                    mma8(acc[mt][nt], a[mt], b[nt]);
        }
        __syncthreads();                        // all warps done reading stage s
    }

    // ---- epilogue: fragment-direct stores ----
    #pragma unroll
    for (int mt = 0; mt < 4; mt++) {
        #pragma unroll
        for (int nt = 0; nt < NTL; nt++) {
            int lr = wm + mt * 16 + g;
            int lc = wn + nt * 8 + 2 * tq;
            if (!VT) {
                float bx = 0.f, by = 0.f;
                if (HAS_BIAS) {
                    float2 bb = *(const float2*)(bias + n0 + lc);
                    bx = bb.x; by = bb.y;
                }
                float2 v0 = make_float2((acc[mt][nt][0] + bx) * alpha,
                                        (acc[mt][nt][1] + by) * alpha);
                float2 v1 = make_float2((acc[mt][nt][2] + bx) * alpha,
                                        (acc[mt][nt][3] + by) * alpha);
                *(float2*)(D0 + (size_t)lr * ldd + lc)       = v0;
                *(float2*)(D0 + (size_t)(lr + 8) * ldd + lc) = v1;
            } else {
                // scatter into v_t[r][h][d][c]; contiguous over c = token column
                int ng0 = n0 + lc, ng1 = ng0 + 1;
                float b0v = bias[ng0], b1v = bias[ng1];
                size_t cb0 = ((size_t)(rr * H_ + (ng0 >> 6)) * HD_ + (ng0 & 63)) * C_ + cc0;
                size_t cb1 = ((size_t)(rr * H_ + (ng1 >> 6)) * HD_ + (ng1 & 63)) * C_ + cc0;
                D[cb0 + lr]     = (acc[mt][nt][0] + b0v) * alpha;
                D[cb1 + lr]     = (acc[mt][nt][1] + b1v) * alpha;
                D[cb0 + lr + 8] = (acc[mt][nt][2] + b0v) * alpha;
                D[cb1 + lr + 8] = (acc[mt][nt][3] + b1v) * alpha;
            }
        }
    }
}

// ---------------------------------------------------------------------------
// Masked softmax over j (diag masked). One block (256 thr) per (h,i).
// Writes probs in-place into lg AND into d_out attn_probs slot.
// ---------------------------------------------------------------------------
__global__ __launch_bounds__(256) void softmax_kernel(
    float* __restrict__ lg, float* __restrict__ probs_out)
{
    __shared__ float redmax[8];
    __shared__ float redsum[8];

    int row = blockIdx.x;             // h*C_ + i
    int i   = row % C_;
    float* base = lg + (size_t)row * C_;
    int t = threadIdx.x;

    float x0 = base[t];
    float x1 = base[t + 256];
    if (t == i)       x0 = -1e9f;
    if (t + 256 == i) x1 = -1e9f;

    float m = fmaxf(x0, x1);
    #pragma unroll
    for (int o = 16; o > 0; o >>= 1)
        m = fmaxf(m, __shfl_xor_sync(0xffffffffu, m, o));
    if ((t & 31) == 0) redmax[t >> 5] = m;
    __syncthreads();
    float M = redmax[0];
    #pragma unroll
    for (int w = 1; w < 8; w++) M = fmaxf(M, redmax[w]);

    float e0 = __expf(x0 - M);
    float e1 = __expf(x1 - M);
    float s = e0 + e1;
    #pragma unroll
    for (int o = 16; o > 0; o >>= 1)
        s += __shfl_xor_sync(0xffffffffu, s, o);
    if ((t & 31) == 0) redsum[t >> 5] = s;
    __syncthreads();
    float S = 0.f;
    #pragma unroll
    for (int w = 0; w < 8; w++) S += redsum[w];
    float inv = 1.f / S;

    float p0 = e0 * inv, p1 = e1 * inv;
    base[t]       = p0;
    base[t + 256] = p1;
    float* po = probs_out + (size_t)row * C_;
    po[t]       = p0;
    po[t + 256] = p1;
}

__global__ void copy_l_kernel(const float* __restrict__ l, float* __restrict__ out)
{
    int t = threadIdx.x;
    if (t < H_) out[t] = l[t];
}

// ---------------------------------------------------------------------------
extern "C" void kernel_launch(void* const* d_in, const int* in_sizes, int n_in,
                              void* d_out, int out_size)
{
    const float* x  = (const float*)d_in[0];
    // d_in[1] = network (unused by reference outputs)
    const float* Wq = (const float*)d_in[2];
    const float* bq = (const float*)d_in[3];
    const float* Wk = (const float*)d_in[4];
    const float* bk = (const float*)d_in[5];
    const float* Wv = (const float*)d_in[6];
    const float* bv = (const float*)d_in[7];
    const float* Wo = (const float*)d_in[8];
    const float* bo = (const float*)d_in[9];
    const float* l  = (const float*)d_in[10];
    float* out = (float*)d_out;

    float* q   = nullptr; cudaGetSymbolAddress((void**)&q,   g_q);
    float* k   = nullptr; cudaGetSymbolAddress((void**)&k,   g_k);
    float* vt  = nullptr; cudaGetSymbolAddress((void**)&vt,  g_vt);
    float* ctx = nullptr; cudaGetSymbolAddress((void**)&ctx, g_ctx);
    float* lg  = nullptr; cudaGetSymbolAddress((void**)&lg,  g_lg);

    // dynamic smem: 2 stages * (BM+BN) * 36 words * 4B
    const int smP = 2 * (256 + 128) * 36 * 4;   // 110592
    const int smL = 2 * (128 + 128) * 36 * 4;   // 73728
    const int smC = 2 * (128 +  64) * 36 * 4;   // 55296

    cudaFuncSetAttribute(mma_gemm<256, 128, 2, 24, 0, true, false>,
                         cudaFuncAttributeMaxDynamicSharedMemorySize, smP);
    cudaFuncSetAttribute(mma_gemm<256, 128, 2, 24, 0, true, true>,
                         cudaFuncAttributeMaxDynamicSharedMemorySize, smP);
    cudaFuncSetAttribute(mma_gemm<128, 128, 4, 128, 1, false, false>,
                         cudaFuncAttributeMaxDynamicSharedMemorySize, smL);
    cudaFuncSetAttribute(mma_gemm<128, 64, 2, 16, 2, false, false>,
                         cudaFuncAttributeMaxDynamicSharedMemorySize, smC);

    const float scaling = (1.0f / 8.0f) / 8.0f;  // D^-0.5 / sqrt(R) = 1/64

    dim3 pg(NTOK / 256, E_ / 128);               // (128, 6)
    mma_gemm<256, 128, 2, 24, 0, true, false><<<pg, 256, smP>>>(x, Wq, bq, q, scaling);
    mma_gemm<256, 128, 2, 24, 0, true, false><<<pg, 256, smP>>>(x, Wk, bk, k, 1.0f);
    mma_gemm<256, 128, 2, 24, 0, true, true ><<<pg, 256, smP>>>(x, Wv, bv, vt, 1.0f);

    dim3 lgr(C_ / 128, C_ / 128, H_);            // (4, 4, 12)
    mma_gemm<128, 128, 4, 128, 1, false, false><<<lgr, 256, smL>>>(q, k, nullptr, lg, 1.0f);

    softmax_kernel<<<H_ * C_, 256>>>(lg, out + OFF_PROBS);

    dim3 cg(C_ / 128, H_, R_);                   // (4, 12, 64)
    mma_gemm<128, 64, 2, 16, 2, false, false><<<cg, 128, smC>>>(lg, vt, nullptr, ctx, 1.0f);

    mma_gemm<256, 128, 2, 24, 0, true, false><<<pg, 256, smP>>>(ctx, Wo, bo, out, 1.0f);

    copy_l_kernel<<<1, 32>>>(l, out + OFF_L);
}

// round 6
// speedup vs baseline: 3.7313x; 1.1773x over previous
#include <cuda_runtime.h>
#include <cstdint>

// Problem constants
#define R_   64
#define C_   512
#define E_   768
#define H_   12
#define HD_  64
#define NTOK (R_ * C_)          // 32768 tokens (B=1)
#define BKC  32                 // k-chunk size

// Output layout inside d_out (flattened tuple: output, attn_probs, l)
#define OFF_PROBS ((size_t)NTOK * E_)
#define OFF_L     (OFF_PROBS + (size_t)H_ * C_ * C_)

// Scratch (device globals -- no allocation allowed)
__device__ float g_xr [(size_t)NTOK * E_];   // x rounded to tf32
__device__ float g_wr [4][(size_t)E_ * E_];  // Wq,Wk,Wv,Wo rounded
__device__ float g_q  [(size_t)NTOK * E_];
__device__ float g_k  [(size_t)NTOK * E_];
__device__ float g_vt [(size_t)NTOK * E_];   // [r][h][d][c] transposed V
__device__ float g_ctx[(size_t)NTOK * E_];
__device__ float g_lg [(size_t)H_ * C_ * C_];

// ============================ helpers ============================
__device__ __forceinline__ uint32_t smem_u32(const void* p) {
    uint32_t a;
    asm("{ .reg .u64 t; cvta.to.shared.u64 t, %1; cvt.u32.u64 %0, t; }" : "=r"(a) : "l"(p));
    return a;
}
__device__ __forceinline__ void cp16(uint32_t saddr, const float* gptr) {
    size_t ga = __cvta_generic_to_global(gptr);
    asm volatile("cp.async.cg.shared.global [%0], [%1], 16;" :: "r"(saddr), "l"(ga) : "memory");
}
// round fp32 -> nearest tf32-representable fp32 (low 13 mantissa bits zero)
__device__ __forceinline__ float tf32f(float f) {
    uint32_t o;
    asm("cvt.rna.tf32.f32 %0, %1;" : "=r"(o) : "f"(f));
    return __uint_as_float(o);
}
// D += A(16x8,row) * B(8x8,col)  -- tf32 inputs, fp32 accum
__device__ __forceinline__ void mma8(float* c, const uint32_t* a, const uint32_t* b) {
    asm volatile(
        "mma.sync.aligned.m16n8k8.row.col.f32.tf32.tf32.f32 "
        "{%0,%1,%2,%3}, {%4,%5,%6,%7}, {%8,%9}, {%0,%1,%2,%3};"
        : "+f"(c[0]), "+f"(c[1]), "+f"(c[2]), "+f"(c[3])
        : "r"(a[0]), "r"(a[1]), "r"(a[2]), "r"(a[3]), "r"(b[0]), "r"(b[1]));
}

// elementwise tf32 rounding prepass (float4 vectorized)
__global__ __launch_bounds__(256) void round_kernel(
    const float* __restrict__ in, float* __restrict__ out, int n4)
{
    int i = blockIdx.x * 256 + threadIdx.x;
    if (i < n4) {
        float4 v = ((const float4*)in)[i];
        v.x = tf32f(v.x); v.y = tf32f(v.y); v.z = tf32f(v.z); v.w = tf32f(v.w);
        ((float4*)out)[i] = v;
    }
}

// ============================================================================
// tf32 mma.sync GEMM-NT: D[m][n] = alpha * (sum_k A[m][k]*B[n][k] + bias[n])
// ALL operands must be pre-rounded to tf32 (no cvt in mainloop).
//   MODE 0 (PROJ):   A=xr[M,768], B=Wr[768,768]. grid(M/BM, 768/BN).
//                    VT=true scatters result into v_t[r][h][d][c].
//   MODE 1 (LOGITS): per head h: D[i,j] = sum_{r,d} q[r,i,h,d]*k[r,j,h,d]
//                    grid(i/BM, j/BN, h). K=4096, chunk kc -> (r=kc>>1, dhalf=kc&1).
//   MODE 2 (CTX):    per (h,r): D[i,d] = sum_j probs[h,i,j]*v_t[r,h,d,j]
//                    grid(i/BM, h, r). K=512.
// RND: round result to tf32 before store (for buffers feeding another MMA).
// 2-stage cp.async pipeline, BK=32, warp tile 64x32, m16n8k8 tf32 MMA.
// ============================================================================
template<int BM, int BN, int WC, int NCH, int MODE, bool HAS_BIAS, bool VT,
         bool RND, int MINB>
__global__ __launch_bounds__((BM / 64) * WC * 32, MINB)
void mma_gemm(const float* __restrict__ A, const float* __restrict__ B,
              const float* __restrict__ bias, float* __restrict__ D, float alpha)
{
    constexpr int WR   = BM / 64;
    constexpr int NT   = WR * WC * 32;
    constexpr int WN   = BN / WC;
    constexpr int NTL  = WN / 8;
    constexpr int LDSw = BKC + 4;               // padded row stride (words)
    constexpr int STG  = (BM + BN) * LDSw;      // words per stage
    constexpr int IA   = BM * (BKC / 4) / NT;   // A float4 loads per thread
    constexpr int IB   = BN * (BKC / 4) / NT;

    extern __shared__ __align__(16) uint32_t sm[];
    const uint32_t sbase = smem_u32(sm);
    const int tid = threadIdx.x, wid = tid >> 5, lane = tid & 31;
    const int g = lane >> 2, tq = lane & 3;
    const int wm = (wid / WC) * 64, wn = (wid % WC) * WN;

    // ---- per-CTA operand/result decode ----
    const float* A0; const float* B0; float* D0 = nullptr;
    size_t lda, ldb, ldd = 0;
    int n0 = 0, rr = 0, cc0 = 0;
    if (MODE == 0) {
        int m0 = blockIdx.x * BM; n0 = blockIdx.y * BN;
        lda = E_; ldb = E_; ldd = E_;
        A0 = A + (size_t)m0 * lda;
        B0 = B + (size_t)n0 * ldb;
        D0 = D + (size_t)m0 * ldd + n0;
        rr = m0 / C_; cc0 = m0 % C_;            // BM<=512 & aligned: one r per block
    } else if (MODE == 1) {
        int i0 = blockIdx.x * BM, j0 = blockIdx.y * BN, h = blockIdx.z;
        lda = E_; ldb = E_; ldd = C_;
        A0 = A + (size_t)i0 * E_ + h * HD_;
        B0 = B + (size_t)j0 * E_ + h * HD_;
        D0 = D + ((size_t)h * C_ + i0) * C_ + j0;
    } else {
        int i0 = blockIdx.x * BM, h = blockIdx.y, r = blockIdx.z;
        lda = C_; ldb = C_; ldd = E_;
        A0 = A + ((size_t)h * C_ + i0) * C_;
        B0 = B + ((size_t)(r * H_ + h) * HD_) * C_;
        D0 = D + ((size_t)r * C_ + i0) * E_ + h * HD_;
    }

    auto issue = [&](int kc, int s) {
        size_t koff = (MODE == 1)
            ? ((size_t)(kc >> 1) * ((size_t)C_ * E_) + (size_t)(kc & 1) * BKC)
            : (size_t)kc * BKC;
        const float* Ab = A0 + koff;
        const float* Bb = B0 + koff;
        #pragma unroll
        for (int it = 0; it < IA; it++) {
            int idx = tid + it * NT, row = idx >> 3, cw = (idx & 7) * 4;
            cp16(sbase + (uint32_t)(s * STG + row * LDSw + cw) * 4u,
                 Ab + (size_t)row * lda + cw);
        }
        #pragma unroll
        for (int it = 0; it < IB; it++) {
            int idx = tid + it * NT, row = idx >> 3, cw = (idx & 7) * 4;
            cp16(sbase + (uint32_t)(s * STG + BM * LDSw + row * LDSw + cw) * 4u,
                 Bb + (size_t)row * ldb + cw);
        }
        asm volatile("cp.async.commit_group;" ::: "memory");
    };

    float acc[4][NTL][4];
    #pragma unroll
    for (int mt = 0; mt < 4; mt++)
        #pragma unroll
        for (int nt = 0; nt < NTL; nt++)
            #pragma unroll
            for (int i = 0; i < 4; i++) acc[mt][nt][i] = 0.f;

    issue(0, 0);
    #pragma unroll 1
    for (int kc = 0; kc < NCH; kc++) {
        const int s = kc & 1;
        if (kc + 1 < NCH) {
            issue(kc + 1, s ^ 1);               // stage s^1 free (synced last iter)
            asm volatile("cp.async.wait_group 1;" ::: "memory");
        } else {
            asm volatile("cp.async.wait_group 0;" ::: "memory");
        }
        __syncthreads();                        // chunk kc visible block-wide

        const uint32_t* sA = sm + s * STG + wm * LDSw;
        const uint32_t* sB = sm + s * STG + BM * LDSw + wn * LDSw;
        #pragma unroll
        for (int ks = 0; ks < BKC / 8; ks++) {
            const int k0 = ks * 8;
            uint32_t a[4][4], b[NTL][2];
            #pragma unroll
            for (int mt = 0; mt < 4; mt++) {
                int rb = mt * 16;
                a[mt][0] = sA[(rb + g    ) * LDSw + k0 + tq    ];
                a[mt][1] = sA[(rb + g + 8) * LDSw + k0 + tq    ];
                a[mt][2] = sA[(rb + g    ) * LDSw + k0 + tq + 4];
                a[mt][3] = sA[(rb + g + 8) * LDSw + k0 + tq + 4];
            }
            #pragma unroll
            for (int nt = 0; nt < NTL; nt++) {
                int cb = nt * 8;
                b[nt][0] = sB[(cb + g) * LDSw + k0 + tq    ];
                b[nt][1] = sB[(cb + g) * LDSw + k0 + tq + 4];
            }
            #pragma unroll
            for (int mt = 0; mt < 4; mt++)
                #pragma unroll
                for (int nt = 0; nt < NTL; nt++)
                    mma8(acc[mt][nt], a[mt], b[nt]);
        }
        __syncthreads();                        // all warps done reading stage s
    }

    // ---- epilogue: fragment-direct stores ----
    #pragma unroll
    for (int mt = 0; mt < 4; mt++) {
        #pragma unroll
        for (int nt = 0; nt < NTL; nt++) {
            int lr = wm + mt * 16 + g;
            int lc = wn + nt * 8 + 2 * tq;
            if (!VT) {
                float bx = 0.f, by = 0.f;
                if (HAS_BIAS) {
                    float2 bb = *(const float2*)(bias + n0 + lc);
                    bx = bb.x; by = bb.y;
                }
                float v0 = (acc[mt][nt][0] + bx) * alpha;
                float v1 = (acc[mt][nt][1] + by) * alpha;
                float v2 = (acc[mt][nt][2] + bx) * alpha;
                float v3 = (acc[mt][nt][3] + by) * alpha;
                if (RND) { v0 = tf32f(v0); v1 = tf32f(v1); v2 = tf32f(v2); v3 = tf32f(v3); }
                *(float2*)(D0 + (size_t)lr * ldd + lc)       = make_float2(v0, v1);
                *(float2*)(D0 + (size_t)(lr + 8) * ldd + lc) = make_float2(v2, v3);
            } else {
                // scatter into v_t[r][h][d][c]; contiguous over c = token column
                int ng0 = n0 + lc, ng1 = ng0 + 1;
                float b0v = bias[ng0], b1v = bias[ng1];
                size_t cb0 = ((size_t)(rr * H_ + (ng0 >> 6)) * HD_ + (ng0 & 63)) * C_ + cc0;
                size_t cb1 = ((size_t)(rr * H_ + (ng1 >> 6)) * HD_ + (ng1 & 63)) * C_ + cc0;
                float v0 = (acc[mt][nt][0] + b0v) * alpha;
                float v1 = (acc[mt][nt][1] + b1v) * alpha;
                float v2 = (acc[mt][nt][2] + b0v) * alpha;
                float v3 = (acc[mt][nt][3] + b1v) * alpha;
                if (RND) { v0 = tf32f(v0); v1 = tf32f(v1); v2 = tf32f(v2); v3 = tf32f(v3); }
                D[cb0 + lr]     = v0;
                D[cb1 + lr]     = v1;
                D[cb0 + lr + 8] = v2;
                D[cb1 + lr + 8] = v3;
            }
        }
    }
}

// ---------------------------------------------------------------------------
// Masked softmax over j (diag masked). One block (256 thr) per (h,i).
// Writes tf32-rounded probs into lg (feeds ctx MMA) and exact probs to d_out.
// ---------------------------------------------------------------------------
__global__ __launch_bounds__(256) void softmax_kernel(
    float* __restrict__ lg, float* __restrict__ probs_out)
{
    __shared__ float redmax[8];
    __shared__ float redsum[8];

    int row = blockIdx.x;             // h*C_ + i
    int i   = row % C_;
    float* base = lg + (size_t)row * C_;
    int t = threadIdx.x;

    float x0 = base[t];
    float x1 = base[t + 256];
    if (t == i)       x0 = -1e9f;
    if (t + 256 == i) x1 = -1e9f;

    float m = fmaxf(x0, x1);
    #pragma unroll
    for (int o = 16; o > 0; o >>= 1)
        m = fmaxf(m, __shfl_xor_sync(0xffffffffu, m, o));
    if ((t & 31) == 0) redmax[t >> 5] = m;
    __syncthreads();
    float M = redmax[0];
    #pragma unroll
    for (int w = 1; w < 8; w++) M = fmaxf(M, redmax[w]);

    float e0 = __expf(x0 - M);
    float e1 = __expf(x1 - M);
    float s = e0 + e1;
    #pragma unroll
    for (int o = 16; o > 0; o >>= 1)
        s += __shfl_xor_sync(0xffffffffu, s, o);
    if ((t & 31) == 0) redsum[t >> 5] = s;
    __syncthreads();
    float S = 0.f;
    #pragma unroll
    for (int w = 0; w < 8; w++) S += redsum[w];
    float inv = 1.f / S;

    float p0 = e0 * inv, p1 = e1 * inv;
    base[t]       = tf32f(p0);        // rounded copy for the ctx MMA
    base[t + 256] = tf32f(p1);
    float* po = probs_out + (size_t)row * C_;
    po[t]       = p0;                 // exact copy for the attn_probs output
    po[t + 256] = p1;
}

__global__ void copy_l_kernel(const float* __restrict__ l, float* __restrict__ out)
{
    int t = threadIdx.x;
    if (t < H_) out[t] = l[t];
}

// ---------------------------------------------------------------------------
extern "C" void kernel_launch(void* const* d_in, const int* in_sizes, int n_in,
                              void* d_out, int out_size)
{
    const float* x  = (const float*)d_in[0];
    // d_in[1] = network (unused by reference outputs)
    const float* Wq = (const float*)d_in[2];
    const float* bq = (const float*)d_in[3];
    const float* Wk = (const float*)d_in[4];
    const float* bk = (const float*)d_in[5];
    const float* Wv = (const float*)d_in[6];
    const float* bv = (const float*)d_in[7];
    const float* Wo = (const float*)d_in[8];
    const float* bo = (const float*)d_in[9];
    const float* l  = (const float*)d_in[10];
    float* out = (float*)d_out;

    float* xr  = nullptr; cudaGetSymbolAddress((void**)&xr,  g_xr);
    float* wr  = nullptr; cudaGetSymbolAddress((void**)&wr,  g_wr);
    float* q   = nullptr; cudaGetSymbolAddress((void**)&q,   g_q);
    float* k   = nullptr; cudaGetSymbolAddress((void**)&k,   g_k);
    float* vt  = nullptr; cudaGetSymbolAddress((void**)&vt,  g_vt);
    float* ctx = nullptr; cudaGetSymbolAddress((void**)&ctx, g_ctx);
    float* lg  = nullptr; cudaGetSymbolAddress((void**)&lg,  g_lg);
    float* wqr = wr;
    float* wkr = wr + (size_t)E_ * E_;
    float* wvr = wr + 2 * (size_t)E_ * E_;
    float* wor = wr + 3 * (size_t)E_ * E_;

    // dynamic smem: 2 stages * (BM+BN) * 36 words * 4B
    const int smP = 2 * (128 + 128) * 36 * 4;   // 73728
    const int smL = 2 * (128 +  64) * 36 * 4;   // 55296

    cudaFuncSetAttribute(mma_gemm<128, 128, 4, 24, 0, true, false, true, 2>,
                         cudaFuncAttributeMaxDynamicSharedMemorySize, smP);
    cudaFuncSetAttribute(mma_gemm<128, 128, 4, 24, 0, true, true, true, 2>,
                         cudaFuncAttributeMaxDynamicSharedMemorySize, smP);
    cudaFuncSetAttribute(mma_gemm<128, 128, 4, 24, 0, true, false, false, 2>,
                         cudaFuncAttributeMaxDynamicSharedMemorySize, smP);
    cudaFuncSetAttribute(mma_gemm<128, 64, 2, 128, 1, false, false, false, 4>,
                         cudaFuncAttributeMaxDynamicSharedMemorySize, smL);
    cudaFuncSetAttribute(mma_gemm<128, 64, 2, 16, 2, false, false, true, 4>,
                         cudaFuncAttributeMaxDynamicSharedMemorySize, smL);

    const float scaling = (1.0f / 8.0f) / 8.0f;  // D^-0.5 / sqrt(R) = 1/64

    // ---- prepass: round x and weights to tf32 once ----
    const int xn4 = (NTOK * E_) / 4;             // 6291456
    const int wn4 = (E_ * E_) / 4;               // 147456
    round_kernel<<<(xn4 + 255) / 256, 256>>>(x, xr, xn4);
    round_kernel<<<(wn4 + 255) / 256, 256>>>(Wq, wqr, wn4);
    round_kernel<<<(wn4 + 255) / 256, 256>>>(Wk, wkr, wn4);
    round_kernel<<<(wn4 + 255) / 256, 256>>>(Wv, wvr, wn4);
    round_kernel<<<(wn4 + 255) / 256, 256>>>(Wo, wor, wn4);

    // ---- projections (outputs rounded: they feed the logits/ctx MMAs) ----
    dim3 pg(NTOK / 128, E_ / 128);               // (256, 6)
    mma_gemm<128, 128, 4, 24, 0, true, false, true, 2><<<pg, 256, smP>>>(xr, wqr, bq, q, scaling);
    mma_gemm<128, 128, 4, 24, 0, true, false, true, 2><<<pg, 256, smP>>>(xr, wkr, bk, k, 1.0f);
    mma_gemm<128, 128, 4, 24, 0, true, true,  true, 2><<<pg, 256, smP>>>(xr, wvr, bv, vt, 1.0f);

    // ---- tied-row logits (output NOT rounded: feeds softmax) ----
    dim3 lgr(C_ / 128, C_ / 64, H_);             // (4, 8, 12)
    mma_gemm<128, 64, 2, 128, 1, false, false, false, 4><<<lgr, 128, smL>>>(q, k, nullptr, lg, 1.0f);

    softmax_kernel<<<H_ * C_, 256>>>(lg, out + OFF_PROBS);

    // ---- context (output rounded: feeds O-projection MMA) ----
    dim3 cg(C_ / 128, H_, R_);                   // (4, 12, 64)
    mma_gemm<128, 64, 2, 16, 2, false, false, true, 4><<<cg, 128, smL>>>(lg, vt, nullptr, ctx, 1.0f);

    // ---- output projection (exact fp32 out) ----
    mma_gemm<128, 128, 4, 24, 0, true, false, false, 2><<<pg, 256, smP>>>(ctx, wor, bo, out, 1.0f);

    copy_l_kernel<<<1, 32>>>(l, out + OFF_L);
}